// round 7
// baseline (speedup 1.0000x reference)
#include <cuda_runtime.h>
#include <cstdint>

#define B_   4096
#define XD   128
#define YD   64
#define T_   200
#define LAT  100
#define G3   300
#define CH   50
#define NBK  296           // 2 blocks per SM on 148 SMs, exactly balanced
#define NT   512           // 16 warps/block; 2 blocks/SM -> 8 warps/SMSP

// SMEM layout (float offsets), per block: 19212 floats = 76848 bytes
#define OFF_BIH 0          // [300]
#define OFF_BHH 300        // [300]
#define OFF_BL1 600        // [100]
#define OFF_BL2 700        // [64]
#define OFF_H   764        // [100][20]  ([k][r])   2000
#define OFF_AX  2764       // [128][16]  ([k][r])   2048
#define OFF_YP  4812       // [64][17]   ([d][r])   1088
#define OFF_P0  5900       // 8 partial buffers [16][104] each
#define PSTR    1664
#define OFF_O1  OFF_P0     // [100][20] overlays P0/P1 (barrier-separated)
#define SMEM_FLOATS (OFF_P0 + 8 * PSTR)   // 19212

__device__ __forceinline__ float fsig(float x) {
    return __fdividef(1.0f, 1.0f + __expf(-x));
}
__device__ __forceinline__ float ftanh_(float x) {
    float e = __expf(2.0f * x);
    return 1.0f - __fdividef(2.0f, e + 1.0f);
}

// 8-row x 4-col accumulate: A broadcast from SMEM (stride lda), W from gmem (stride G3)
__device__ __forceinline__ void accum8(
    float acc[8][4], const float* __restrict__ sa, int lda, int r0,
    const float* __restrict__ Wp, int k0, int k1)
{
#pragma unroll 2
    for (int k = k0; k < k1; k++) {
        const float4 a0 = *(const float4*)&sa[k * lda + r0];
        const float4 a1 = *(const float4*)&sa[k * lda + r0 + 4];
        const float4 w  = __ldg((const float4*)&Wp[k * G3]);
        acc[0][0] = fmaf(a0.x, w.x, acc[0][0]); acc[0][1] = fmaf(a0.x, w.y, acc[0][1]);
        acc[0][2] = fmaf(a0.x, w.z, acc[0][2]); acc[0][3] = fmaf(a0.x, w.w, acc[0][3]);
        acc[1][0] = fmaf(a0.y, w.x, acc[1][0]); acc[1][1] = fmaf(a0.y, w.y, acc[1][1]);
        acc[1][2] = fmaf(a0.y, w.z, acc[1][2]); acc[1][3] = fmaf(a0.y, w.w, acc[1][3]);
        acc[2][0] = fmaf(a0.z, w.x, acc[2][0]); acc[2][1] = fmaf(a0.z, w.y, acc[2][1]);
        acc[2][2] = fmaf(a0.z, w.z, acc[2][2]); acc[2][3] = fmaf(a0.z, w.w, acc[2][3]);
        acc[3][0] = fmaf(a0.w, w.x, acc[3][0]); acc[3][1] = fmaf(a0.w, w.y, acc[3][1]);
        acc[3][2] = fmaf(a0.w, w.z, acc[3][2]); acc[3][3] = fmaf(a0.w, w.w, acc[3][3]);
        acc[4][0] = fmaf(a1.x, w.x, acc[4][0]); acc[4][1] = fmaf(a1.x, w.y, acc[4][1]);
        acc[4][2] = fmaf(a1.x, w.z, acc[4][2]); acc[4][3] = fmaf(a1.x, w.w, acc[4][3]);
        acc[5][0] = fmaf(a1.y, w.x, acc[5][0]); acc[5][1] = fmaf(a1.y, w.y, acc[5][1]);
        acc[5][2] = fmaf(a1.y, w.z, acc[5][2]); acc[5][3] = fmaf(a1.y, w.w, acc[5][3]);
        acc[6][0] = fmaf(a1.z, w.x, acc[6][0]); acc[6][1] = fmaf(a1.z, w.y, acc[6][1]);
        acc[6][2] = fmaf(a1.z, w.z, acc[6][2]); acc[6][3] = fmaf(a1.z, w.w, acc[6][3]);
        acc[7][0] = fmaf(a1.w, w.x, acc[7][0]); acc[7][1] = fmaf(a1.w, w.y, acc[7][1]);
        acc[7][2] = fmaf(a1.w, w.z, acc[7][2]); acc[7][3] = fmaf(a1.w, w.w, acc[7][3]);
    }
}

extern "C" __global__ void __launch_bounds__(NT, 2) gru_kernel(
    const float* __restrict__ x, const float* __restrict__ y, const void* __restrict__ ymask,
    const float* __restrict__ Wmu1, const float* __restrict__ bmu1,
    const float* __restrict__ Wmu2, const float* __restrict__ bmu2,
    const float* __restrict__ Wih, const float* __restrict__ bih,
    const float* __restrict__ Whh, const float* __restrict__ bhh,
    const float* __restrict__ Wl1, const float* __restrict__ bl1,
    const float* __restrict__ Wl2, const float* __restrict__ bl2,
    const float* __restrict__ Wc1, const float* __restrict__ bc1,
    const float* __restrict__ Wc2, const float* __restrict__ bc2,
    float* __restrict__ out, int has_cls)
{
    extern __shared__ float sm[];
    const int tid  = threadIdx.x;
    const int lane = tid & 31;
    const int wid  = tid >> 5;        // 0..15
    const int b0   = (B_ * blockIdx.x) / NBK;
    const int nr   = (B_ * (blockIdx.x + 1)) / NBK - b0;   // 13 or 14 rows
    const int j0   = lane * 4;        // lanes<25 cover 100 cols

    // ---- stage biases; zero y_prev ----
    for (int i = tid; i < G3; i += NT) { sm[OFF_BIH + i] = bih[i]; sm[OFF_BHH + i] = bhh[i]; }
    for (int i = tid; i < LAT; i += NT) sm[OFF_BL1 + i] = bl1[i];
    for (int i = tid; i < YD;  i += NT) sm[OFF_BL2 + i] = bl2[i];
    for (int i = tid; i < YD * 17; i += NT) sm[OFF_YP + i] = 0.f;

    // ---- mask dtype detection (uint8 / int32 / float32), deterministic ----
    const unsigned word = ((const unsigned*)ymask)[tid];
    const int big = __syncthreads_or((word & 0xFEFEFEFEu) != 0u);  // any byte > 1 -> f32
    const int odd = __syncthreads_or((word & 0xFFFFFF00u) != 0u);  // upper bytes set -> u8
    const int mode = big ? 2 : (odd ? 0 : 1);

    // ---- stage x into AX ([k][16]); rows >= nr zeroed ----
#pragma unroll
    for (int i = 0; i < 4; i++) {
        const int e = tid + NT * i;       // 2048 = 16r x 128k
        const int r = e & 15, k = e >> 4;
        sm[OFF_AX + k * 16 + r] = (r < nr) ? __ldg(&x[(size_t)(b0 + r) * XD + k]) : 0.f;
    }
    __syncthreads();

    // ---- h0: tmp = tanh(x @ Wmu1 + bmu1) -> O1; h0 = tmp @ Wmu2 + bmu2 -> H ----
    if (lane < 25) {
        float acc[4] = {0.f, 0.f, 0.f, 0.f};
#pragma unroll 4
        for (int k = 0; k < XD; k++) {
            const float a = sm[OFF_AX + k * 16 + wid];
            const float4 wv = __ldg((const float4*)&Wmu1[k * LAT + j0]);
            acc[0] = fmaf(a, wv.x, acc[0]); acc[1] = fmaf(a, wv.y, acc[1]);
            acc[2] = fmaf(a, wv.z, acc[2]); acc[3] = fmaf(a, wv.w, acc[3]);
        }
        const float4 bb = __ldg((const float4*)&bmu1[j0]);
        sm[OFF_O1 + (j0 + 0) * 20 + wid] = ftanh_(acc[0] + bb.x);
        sm[OFF_O1 + (j0 + 1) * 20 + wid] = ftanh_(acc[1] + bb.y);
        sm[OFF_O1 + (j0 + 2) * 20 + wid] = ftanh_(acc[2] + bb.z);
        sm[OFF_O1 + (j0 + 3) * 20 + wid] = ftanh_(acc[3] + bb.w);
    }
    __syncthreads();
    if (lane < 25) {
        float acc[4] = {0.f, 0.f, 0.f, 0.f};
#pragma unroll 4
        for (int k = 0; k < LAT; k++) {
            const float a = sm[OFF_O1 + k * 20 + wid];
            const float4 wv = __ldg((const float4*)&Wmu2[k * LAT + j0]);
            acc[0] = fmaf(a, wv.x, acc[0]); acc[1] = fmaf(a, wv.y, acc[1]);
            acc[2] = fmaf(a, wv.z, acc[2]); acc[3] = fmaf(a, wv.w, acc[3]);
        }
        const float4 bb = __ldg((const float4*)&bmu2[j0]);
        // note: O1 overlays P-space; write H after all reads of O1 done within same warp row
        sm[OFF_H + (j0 + 0) * 20 + wid] = acc[0] + bb.x;
        sm[OFF_H + (j0 + 1) * 20 + wid] = acc[1] + bb.y;
        sm[OFF_H + (j0 + 2) * 20 + wid] = acc[2] + bb.z;
        sm[OFF_H + (j0 + 3) * 20 + wid] = acc[3] + bb.w;
    }

    // ---- prefetch y/mask for t=0 ----
    float yv[2], mfv[2];
    auto preload = [&](int t) {
#pragma unroll
        for (int i = 0; i < 2; i++) {
            const int e = tid + NT * i;   // 1024 = 16r x 64d
            const int r = e & 15, d = e >> 4;
            if (r < nr) {
                const size_t off = (size_t)(b0 + r) * (YD * T_) + (size_t)d * T_ + t;
                yv[i] = __ldg(&y[off]);
                float m;
                if (mode == 0)      m = (((const unsigned char*)ymask)[off] != 0) ? 1.f : 0.f;
                else if (mode == 1) m = (((const int*)ymask)[off] != 0) ? 1.f : 0.f;
                else                m = (((const float*)ymask)[off] != 0.f) ? 1.f : 0.f;
                mfv[i] = m;
            } else { yv[i] = 0.f; mfv[i] = 0.f; }
        }
    };
    preload(0);
    __syncthreads();

    // ================= main recurrence =================
    for (int t = 0; t < T_; ++t) {
        // -- teacher forcing -> AX ([k][16], k interleaved value/mask) --
#pragma unroll
        for (int i = 0; i < 2; i++) {
            const int e = tid + NT * i;
            const int r = e & 15, d = e >> 4;
            const float m  = mfv[i];
            const float yp = sm[OFF_YP + d * 17 + r];
            const float yin = (m != 0.f) ? yv[i] : yp;
            sm[OFF_AX + (2 * d) * 16 + r]     = yin;
            sm[OFF_AX + (2 * d + 1) * 16 + r] = m;
        }
        if (t + 1 < T_) preload(t + 1);
        __syncthreads();

        // -- phase 1: 8 balanced jobs x 2 row-halves, 8-row microtiles --
        // jobs (k-iters): 0:r_x[0,114) 1:r_x[114,128)+r_h 2:z_x[0,114) 3:z_x[114,128)+z_h
        //                 4:nx[0,64)   5:nx[64,128)        6:nh[0,50)   7:nh[50,100)
        if (lane < 25) {
            float acc[8][4];
#pragma unroll
            for (int i = 0; i < 8; i++)
#pragma unroll
                for (int c = 0; c < 4; c++) acc[i][c] = 0.f;
            const int job = wid >> 1;
            const int rr  = (wid & 1) * 8;
            switch (job) {
            case 0: accum8(acc, sm + OFF_AX, 16, rr, Wih + j0, 0, 114); break;
            case 1: accum8(acc, sm + OFF_AX, 16, rr, Wih + j0, 114, XD);
                    accum8(acc, sm + OFF_H,  20, rr, Whh + j0, 0, LAT); break;
            case 2: accum8(acc, sm + OFF_AX, 16, rr, Wih + 100 + j0, 0, 114); break;
            case 3: accum8(acc, sm + OFF_AX, 16, rr, Wih + 100 + j0, 114, XD);
                    accum8(acc, sm + OFF_H,  20, rr, Whh + 100 + j0, 0, LAT); break;
            case 4: accum8(acc, sm + OFF_AX, 16, rr, Wih + 200 + j0, 0, 64); break;
            case 5: accum8(acc, sm + OFF_AX, 16, rr, Wih + 200 + j0, 64, XD); break;
            case 6: accum8(acc, sm + OFF_H,  20, rr, Whh + 200 + j0, 0, 50); break;
            default: accum8(acc, sm + OFF_H, 20, rr, Whh + 200 + j0, 50, LAT); break;
            }
            float* Pdst = sm + OFF_P0 + job * PSTR + j0;
#pragma unroll
            for (int i = 0; i < 8; i++)
                *(float4*)&Pdst[(rr + i) * 104] =
                    make_float4(acc[i][0], acc[i][1], acc[i][2], acc[i][3]);
        }
        __syncthreads();

        // -- gates: r,z = sigmoid; n = tanh(gxn + r*ghn); h = (1-z)*n + z*h --
#pragma unroll
        for (int it = 0; it < 4; ++it) {
            const int idx = tid + NT * it;    // 1600 = 16r x 100j
            if (idx < 16 * LAT) {
                const int r = idx / LAT;
                const int j = idx - r * LAT;
                const int ro = r * 104 + j;
                const float g_r = sm[OFF_P0 + ro] + sm[OFF_P0 + PSTR + ro]
                                + sm[OFF_BIH + j] + sm[OFF_BHH + j];
                const float g_z = sm[OFF_P0 + 2 * PSTR + ro] + sm[OFF_P0 + 3 * PSTR + ro]
                                + sm[OFF_BIH + 100 + j] + sm[OFF_BHH + 100 + j];
                const float gxn = sm[OFF_P0 + 4 * PSTR + ro] + sm[OFF_P0 + 5 * PSTR + ro]
                                + sm[OFF_BIH + 200 + j];
                const float ghn = sm[OFF_P0 + 6 * PSTR + ro] + sm[OFF_P0 + 7 * PSTR + ro]
                                + sm[OFF_BHH + 200 + j];
                const float rg = fsig(g_r);
                const float z  = fsig(g_z);
                const float n  = ftanh_(gxn + rg * ghn);
                const float hd = sm[OFF_H + j * 20 + r];
                sm[OFF_H + j * 20 + r] = (1.f - z) * n + z * hd;
            }
        }
        __syncthreads();

        // -- GEMM3: o1 = tanh(h @ Wl1 + bl1); 4 row-quads x 4 col-chunks, scalar W --
        if (lane < 25) {
            const int q3 = wid & 3;          // row quad
            const int c3 = wid >> 2;         // col chunk of 25
            const int r3 = q3 << 2;
            const int jc = c3 * 25 + lane;
            float a0 = 0.f, a1 = 0.f, a2 = 0.f, a3 = 0.f;
#pragma unroll 4
            for (int k = 0; k < LAT; k++) {
                const float4 a = *(const float4*)&sm[OFF_H + k * 20 + r3];
                const float w = __ldg(&Wl1[k * LAT + jc]);
                a0 = fmaf(a.x, w, a0); a1 = fmaf(a.y, w, a1);
                a2 = fmaf(a.z, w, a2); a3 = fmaf(a.w, w, a3);
            }
            const float bb = sm[OFF_BL1 + jc];
            sm[OFF_O1 + jc * 20 + r3 + 0] = ftanh_(a0 + bb);
            sm[OFF_O1 + jc * 20 + r3 + 1] = ftanh_(a1 + bb);
            sm[OFF_O1 + jc * 20 + r3 + 2] = ftanh_(a2 + bb);
            sm[OFF_O1 + jc * 20 + r3 + 3] = ftanh_(a3 + bb);
        }
        __syncthreads();

        // -- GEMM4: out_t = o1 @ Wl2 + bl2; warp = 4 cols, all lanes active --
        {
            const int row = lane & 15;                      // 0..15
            const int jc  = (wid << 2) + ((lane >> 4) << 1);// wid*4 + half*2
            float a0 = 0.f, a1 = 0.f;
#pragma unroll 4
            for (int k = 0; k < LAT; k++) {
                const float a = sm[OFF_O1 + k * 20 + row];
                const float2 wv = __ldg((const float2*)&Wl2[k * YD + jc]);
                a0 = fmaf(a, wv.x, a0); a1 = fmaf(a, wv.y, a1);
            }
            const float v0 = a0 + sm[OFF_BL2 + jc];
            const float v1 = a1 + sm[OFF_BL2 + jc + 1];
            if (row < nr) {
                float* op = out + (size_t)(b0 + row) * (YD * T_) + (size_t)jc * T_ + t;
                op[0]  = v0;
                op[T_] = v1;
            }
            sm[OFF_YP + jc * 17 + row]       = v0;
            sm[OFF_YP + (jc + 1) * 17 + row] = v1;
        }
        __syncthreads();
    }

    // ---- classifier: sigmoid(relu(h_T @ Wc1 + bc1) @ Wc2 + bc2) ----
    if (has_cls) {
        float* scr = sm + OFF_P0 + 7 * PSTR;                 // free after loop
        for (int idx = tid; idx < 16 * CH; idx += NT) {      // 800 = 16r x 50c
            const int r = idx & 15, c = idx >> 4;
            float acc = __ldg(&bc1[c]);
            for (int k = 0; k < LAT; k++)
                acc = fmaf(sm[OFF_H + k * 20 + r], __ldg(&Wc1[k * CH + c]), acc);
            scr[c * 16 + r] = fmaxf(acc, 0.f);
        }
        __syncthreads();
        if (tid < nr) {
            float acc = __ldg(&bc2[0]);
            for (int c = 0; c < CH; c++)
                acc = fmaf(scr[c * 16 + tid], __ldg(&Wc2[c]), acc);
            out[(size_t)B_ * YD * T_ + b0 + tid] = fsig(acc);
        }
    }
}

extern "C" void kernel_launch(void* const* d_in, const int* in_sizes, int n_in,
                              void* d_out, int out_size)
{
    cudaFuncSetAttribute(gru_kernel, cudaFuncAttributeMaxDynamicSharedMemorySize,
                         SMEM_FLOATS * (int)sizeof(float));
    const int has_cls = (out_size > B_ * YD * T_) ? 1 : 0;
    gru_kernel<<<NBK, NT, SMEM_FLOATS * sizeof(float)>>>(
        (const float*)d_in[0],   // x
        (const float*)d_in[1],   // y
        d_in[2],                 // y_mask (dtype auto-detected)
        (const float*)d_in[3],  (const float*)d_in[4],   // Wmu1, bmu1
        (const float*)d_in[5],  (const float*)d_in[6],   // Wmu2, bmu2
        (const float*)d_in[11], (const float*)d_in[12],  // Wih, bih
        (const float*)d_in[13], (const float*)d_in[14],  // Whh, bhh
        (const float*)d_in[15], (const float*)d_in[16],  // Wl1, bl1
        (const float*)d_in[17], (const float*)d_in[18],  // Wl2, bl2
        (const float*)d_in[19], (const float*)d_in[20],  // Wc1, bc1
        (const float*)d_in[21], (const float*)d_in[22],  // Wc2, bc2
        (float*)d_out, has_cls);
}

// round 8
// speedup vs baseline: 1.1701x; 1.1701x over previous
#include <cuda_runtime.h>
#include <cstdint>

#define B_   4096
#define XD   128
#define YD   64
#define T_   200
#define LAT  100
#define G3   300
#define CH   50
#define NBK  296           // 2 blocks per SM on 148 SMs, exactly balanced
#define NT   512           // 16 warps/block; 2 blocks/SM -> 8 warps/SMSP

// SMEM layout (float offsets), per block: 24204 floats = 96816 bytes (x2 = 193.6KB/SM)
#define OFF_BIH 0          // [300]
#define OFF_BHH 300        // [300]
#define OFF_BL1 600        // [100]
#define OFF_BL2 700        // [64]
#define OFF_H   764        // [100][20]  ([k][r])   2000
#define OFF_AX  2764       // [128][16]  ([k][r])   2048
#define OFF_YP  4812       // [64][17]   ([d][r])   1088
#define OFF_S0  5900       // 11 partial slabs [16][104] each
#define PSTR    1664
#define OFF_O1  OFF_S0     // [100][20] overlays S0/S1 (barrier-separated)
#define SMEM_FLOATS (OFF_S0 + 11 * PSTR)   // 24204

__device__ __forceinline__ float fsig(float x) {
    return __fdividef(1.0f, 1.0f + __expf(-x));
}
__device__ __forceinline__ float ftanh_(float x) {
    float e = __expf(2.0f * x);
    return 1.0f - __fdividef(2.0f, e + 1.0f);
}

// 8-row x 4-col accumulate: A broadcast from SMEM (stride lda), W from gmem (stride G3)
__device__ __forceinline__ void accum8(
    float acc[8][4], const float* __restrict__ sa, int lda, int r0,
    const float* __restrict__ Wp, int k0, int k1)
{
#pragma unroll 2
    for (int k = k0; k < k1; k++) {
        const float4 a0 = *(const float4*)&sa[k * lda + r0];
        const float4 a1 = *(const float4*)&sa[k * lda + r0 + 4];
        const float4 w  = __ldg((const float4*)&Wp[k * G3]);
        acc[0][0] = fmaf(a0.x, w.x, acc[0][0]); acc[0][1] = fmaf(a0.x, w.y, acc[0][1]);
        acc[0][2] = fmaf(a0.x, w.z, acc[0][2]); acc[0][3] = fmaf(a0.x, w.w, acc[0][3]);
        acc[1][0] = fmaf(a0.y, w.x, acc[1][0]); acc[1][1] = fmaf(a0.y, w.y, acc[1][1]);
        acc[1][2] = fmaf(a0.y, w.z, acc[1][2]); acc[1][3] = fmaf(a0.y, w.w, acc[1][3]);
        acc[2][0] = fmaf(a0.z, w.x, acc[2][0]); acc[2][1] = fmaf(a0.z, w.y, acc[2][1]);
        acc[2][2] = fmaf(a0.z, w.z, acc[2][2]); acc[2][3] = fmaf(a0.z, w.w, acc[2][3]);
        acc[3][0] = fmaf(a0.w, w.x, acc[3][0]); acc[3][1] = fmaf(a0.w, w.y, acc[3][1]);
        acc[3][2] = fmaf(a0.w, w.z, acc[3][2]); acc[3][3] = fmaf(a0.w, w.w, acc[3][3]);
        acc[4][0] = fmaf(a1.x, w.x, acc[4][0]); acc[4][1] = fmaf(a1.x, w.y, acc[4][1]);
        acc[4][2] = fmaf(a1.x, w.z, acc[4][2]); acc[4][3] = fmaf(a1.x, w.w, acc[4][3]);
        acc[5][0] = fmaf(a1.y, w.x, acc[5][0]); acc[5][1] = fmaf(a1.y, w.y, acc[5][1]);
        acc[5][2] = fmaf(a1.y, w.z, acc[5][2]); acc[5][3] = fmaf(a1.y, w.w, acc[5][3]);
        acc[6][0] = fmaf(a1.z, w.x, acc[6][0]); acc[6][1] = fmaf(a1.z, w.y, acc[6][1]);
        acc[6][2] = fmaf(a1.z, w.z, acc[6][2]); acc[6][3] = fmaf(a1.z, w.w, acc[6][3]);
        acc[7][0] = fmaf(a1.w, w.x, acc[7][0]); acc[7][1] = fmaf(a1.w, w.y, acc[7][1]);
        acc[7][2] = fmaf(a1.w, w.z, acc[7][2]); acc[7][3] = fmaf(a1.w, w.w, acc[7][3]);
    }
}
__device__ __forceinline__ void zero8(float acc[8][4]) {
#pragma unroll
    for (int i = 0; i < 8; i++)
#pragma unroll
        for (int c = 0; c < 4; c++) acc[i][c] = 0.f;
}
__device__ __forceinline__ void store8(float* __restrict__ dst, int rr, int j0, float acc[8][4]) {
#pragma unroll
    for (int i = 0; i < 8; i++)
        *(float4*)&dst[(rr + i) * 104 + j0] =
            make_float4(acc[i][0], acc[i][1], acc[i][2], acc[i][3]);
}

extern "C" __global__ void __launch_bounds__(NT, 2) gru_kernel(
    const float* __restrict__ x, const float* __restrict__ y, const void* __restrict__ ymask,
    const float* __restrict__ Wmu1, const float* __restrict__ bmu1,
    const float* __restrict__ Wmu2, const float* __restrict__ bmu2,
    const float* __restrict__ Wih, const float* __restrict__ bih,
    const float* __restrict__ Whh, const float* __restrict__ bhh,
    const float* __restrict__ Wl1, const float* __restrict__ bl1,
    const float* __restrict__ Wl2, const float* __restrict__ bl2,
    const float* __restrict__ Wc1, const float* __restrict__ bc1,
    const float* __restrict__ Wc2, const float* __restrict__ bc2,
    float* __restrict__ out, int has_cls)
{
    extern __shared__ float sm[];
    const int tid  = threadIdx.x;
    const int lane = tid & 31;
    const int wid  = tid >> 5;        // 0..15
    const int b0   = (B_ * blockIdx.x) / NBK;
    const int nr   = (B_ * (blockIdx.x + 1)) / NBK - b0;   // 13 or 14 rows
    const int j0   = lane * 4;        // lanes<25 cover 100 cols

    // ---- stage biases; zero y_prev ----
    for (int i = tid; i < G3; i += NT) { sm[OFF_BIH + i] = bih[i]; sm[OFF_BHH + i] = bhh[i]; }
    for (int i = tid; i < LAT; i += NT) sm[OFF_BL1 + i] = bl1[i];
    for (int i = tid; i < YD;  i += NT) sm[OFF_BL2 + i] = bl2[i];
    for (int i = tid; i < YD * 17; i += NT) sm[OFF_YP + i] = 0.f;

    // ---- mask dtype detection (uint8 / int32 / float32), deterministic ----
    const unsigned word = ((const unsigned*)ymask)[tid];
    const int big = __syncthreads_or((word & 0xFEFEFEFEu) != 0u);  // any byte > 1 -> f32
    const int odd = __syncthreads_or((word & 0xFFFFFF00u) != 0u);  // upper bytes set -> u8
    const int mode = big ? 2 : (odd ? 0 : 1);

    // ---- stage x into AX ([k][16]); rows >= nr zeroed ----
#pragma unroll
    for (int i = 0; i < 4; i++) {
        const int e = tid + NT * i;       // 2048 = 16r x 128k
        const int r = e & 15, k = e >> 4;
        sm[OFF_AX + k * 16 + r] = (r < nr) ? __ldg(&x[(size_t)(b0 + r) * XD + k]) : 0.f;
    }
    __syncthreads();

    // ---- h0: tmp = tanh(x @ Wmu1 + bmu1) -> O1; h0 = tmp @ Wmu2 + bmu2 -> H ----
    if (lane < 25) {
        float acc[4] = {0.f, 0.f, 0.f, 0.f};
#pragma unroll 4
        for (int k = 0; k < XD; k++) {
            const float a = sm[OFF_AX + k * 16 + wid];
            const float4 wv = __ldg((const float4*)&Wmu1[k * LAT + j0]);
            acc[0] = fmaf(a, wv.x, acc[0]); acc[1] = fmaf(a, wv.y, acc[1]);
            acc[2] = fmaf(a, wv.z, acc[2]); acc[3] = fmaf(a, wv.w, acc[3]);
        }
        const float4 bb = __ldg((const float4*)&bmu1[j0]);
        sm[OFF_O1 + (j0 + 0) * 20 + wid] = ftanh_(acc[0] + bb.x);
        sm[OFF_O1 + (j0 + 1) * 20 + wid] = ftanh_(acc[1] + bb.y);
        sm[OFF_O1 + (j0 + 2) * 20 + wid] = ftanh_(acc[2] + bb.z);
        sm[OFF_O1 + (j0 + 3) * 20 + wid] = ftanh_(acc[3] + bb.w);
    }
    __syncthreads();
    if (lane < 25) {
        float acc[4] = {0.f, 0.f, 0.f, 0.f};
#pragma unroll 4
        for (int k = 0; k < LAT; k++) {
            const float a = sm[OFF_O1 + k * 20 + wid];
            const float4 wv = __ldg((const float4*)&Wmu2[k * LAT + j0]);
            acc[0] = fmaf(a, wv.x, acc[0]); acc[1] = fmaf(a, wv.y, acc[1]);
            acc[2] = fmaf(a, wv.z, acc[2]); acc[3] = fmaf(a, wv.w, acc[3]);
        }
        const float4 bb = __ldg((const float4*)&bmu2[j0]);
        sm[OFF_H + (j0 + 0) * 20 + wid] = acc[0] + bb.x;
        sm[OFF_H + (j0 + 1) * 20 + wid] = acc[1] + bb.y;
        sm[OFF_H + (j0 + 2) * 20 + wid] = acc[2] + bb.z;
        sm[OFF_H + (j0 + 3) * 20 + wid] = acc[3] + bb.w;
    }

    // ---- prefetch y/mask for t=0 ----
    float yv[2], mfv[2];
    auto preload = [&](int t) {
#pragma unroll
        for (int i = 0; i < 2; i++) {
            const int e = tid + NT * i;   // 1024 = 16r x 64d
            const int r = e & 15, d = e >> 4;
            if (r < nr) {
                const size_t off = (size_t)(b0 + r) * (YD * T_) + (size_t)d * T_ + t;
                yv[i] = __ldg(&y[off]);
                float m;
                if (mode == 0)      m = (((const unsigned char*)ymask)[off] != 0) ? 1.f : 0.f;
                else if (mode == 1) m = (((const int*)ymask)[off] != 0) ? 1.f : 0.f;
                else                m = (((const float*)ymask)[off] != 0.f) ? 1.f : 0.f;
                mfv[i] = m;
            } else { yv[i] = 0.f; mfv[i] = 0.f; }
        }
    };
    preload(0);
    __syncthreads();

    // ================= main recurrence =================
    for (int t = 0; t < T_; ++t) {
        // -- teacher forcing -> AX ([k][16], k interleaved value/mask) --
#pragma unroll
        for (int i = 0; i < 2; i++) {
            const int e = tid + NT * i;
            const int r = e & 15, d = e >> 4;
            const float m  = mfv[i];
            const float yp = sm[OFF_YP + d * 17 + r];
            const float yin = (m != 0.f) ? yv[i] : yp;
            sm[OFF_AX + (2 * d) * 16 + r]     = yin;
            sm[OFF_AX + (2 * d + 1) * 16 + r] = m;
        }
        if (t + 1 < T_) preload(t + 1);
        __syncthreads();

        // -- phase 1: 8 jobs x 2 row-halves; every warp 85-86 k-iters (FFMA-balanced),
        //    8-row microtiles (half of R6's weight wavefronts). Streams:
        //    r = AX@Wih[:,0:100] + H@Whh[:,0:100]   -> S0+S1+S2
        //    z = AX@Wih[:,100:200] + H@Whh[:,100:200] -> S3+S4+S5+S6
        //    nx = AX@Wih[:,200:300] -> S7+S8 ;  nh = H@Whh[:,200:300] -> S9+S10
        if (lane < 25) {
            float acc[8][4];
            zero8(acc);
            const int job = wid >> 1;
            const int rr  = (wid & 1) * 8;
            float* S = sm + OFF_S0;
            switch (job) {
            case 0:  // r: AX[0,86)
                accum8(acc, sm + OFF_AX, 16, rr, Wih + j0, 0, 86);
                store8(S + 0 * PSTR + j0, rr, 0, acc); break;
            case 1:  // r: AX[86,128) + H[0,44)
                accum8(acc, sm + OFF_AX, 16, rr, Wih + j0, 86, XD);
                accum8(acc, sm + OFF_H,  20, rr, Whh + j0, 0, 44);
                store8(S + 1 * PSTR + j0, rr, 0, acc); break;
            case 2:  // r: H[44,100) -> S2 ; z: AX[0,29) -> S3
                accum8(acc, sm + OFF_H, 20, rr, Whh + j0, 44, LAT);
                store8(S + 2 * PSTR + j0, rr, 0, acc);
                zero8(acc);
                accum8(acc, sm + OFF_AX, 16, rr, Wih + 100 + j0, 0, 29);
                store8(S + 3 * PSTR + j0, rr, 0, acc); break;
            case 3:  // z: AX[29,115)
                accum8(acc, sm + OFF_AX, 16, rr, Wih + 100 + j0, 29, 115);
                store8(S + 4 * PSTR + j0, rr, 0, acc); break;
            case 4:  // z: AX[115,128) + H[0,72)
                accum8(acc, sm + OFF_AX, 16, rr, Wih + 100 + j0, 115, XD);
                accum8(acc, sm + OFF_H,  20, rr, Whh + 100 + j0, 0, 72);
                store8(S + 5 * PSTR + j0, rr, 0, acc); break;
            case 5:  // z: H[72,100) -> S6 ; nx: AX[0,58) -> S7
                accum8(acc, sm + OFF_H, 20, rr, Whh + 100 + j0, 72, LAT);
                store8(S + 6 * PSTR + j0, rr, 0, acc);
                zero8(acc);
                accum8(acc, sm + OFF_AX, 16, rr, Wih + 200 + j0, 0, 58);
                store8(S + 7 * PSTR + j0, rr, 0, acc); break;
            case 6:  // nx: AX[58,128) -> S8 ; nh: H[0,15) -> S9
                accum8(acc, sm + OFF_AX, 16, rr, Wih + 200 + j0, 58, XD);
                store8(S + 8 * PSTR + j0, rr, 0, acc);
                zero8(acc);
                accum8(acc, sm + OFF_H, 20, rr, Whh + 200 + j0, 0, 15);
                store8(S + 9 * PSTR + j0, rr, 0, acc); break;
            default: // nh: H[15,100)
                accum8(acc, sm + OFF_H, 20, rr, Whh + 200 + j0, 15, LAT);
                store8(S + 10 * PSTR + j0, rr, 0, acc); break;
            }
        }
        __syncthreads();

        // -- gates: r,z = sigmoid; n = tanh(gxn + r*ghn); h = (1-z)*n + z*h --
#pragma unroll
        for (int it = 0; it < 4; ++it) {
            const int idx = tid + NT * it;    // 1600 = 16r x 100j
            if (idx < 16 * LAT) {
                const int r = idx / LAT;
                const int j = idx - r * LAT;
                const int ro = r * 104 + j;
                const float* S = sm + OFF_S0;
                const float g_r = S[ro] + S[PSTR + ro] + S[2 * PSTR + ro]
                                + sm[OFF_BIH + j] + sm[OFF_BHH + j];
                const float g_z = S[3 * PSTR + ro] + S[4 * PSTR + ro]
                                + S[5 * PSTR + ro] + S[6 * PSTR + ro]
                                + sm[OFF_BIH + 100 + j] + sm[OFF_BHH + 100 + j];
                const float gxn = S[7 * PSTR + ro] + S[8 * PSTR + ro]
                                + sm[OFF_BIH + 200 + j];
                const float ghn = S[9 * PSTR + ro] + S[10 * PSTR + ro]
                                + sm[OFF_BHH + 200 + j];
                const float rg = fsig(g_r);
                const float z  = fsig(g_z);
                const float n  = ftanh_(gxn + rg * ghn);
                const float hd = sm[OFF_H + j * 20 + r];
                sm[OFF_H + j * 20 + r] = (1.f - z) * n + z * hd;
            }
        }
        __syncthreads();

        // -- GEMM3: o1 = tanh(h @ Wl1 + bl1); 4 row-quads x 4 col-chunks, scalar W --
        if (lane < 25) {
            const int q3 = wid & 3;          // row quad
            const int c3 = wid >> 2;         // col chunk of 25
            const int r3 = q3 << 2;
            const int jc = c3 * 25 + lane;
            float a0 = 0.f, a1 = 0.f, a2 = 0.f, a3 = 0.f;
#pragma unroll 4
            for (int k = 0; k < LAT; k++) {
                const float4 a = *(const float4*)&sm[OFF_H + k * 20 + r3];
                const float w = __ldg(&Wl1[k * LAT + jc]);
                a0 = fmaf(a.x, w, a0); a1 = fmaf(a.y, w, a1);
                a2 = fmaf(a.z, w, a2); a3 = fmaf(a.w, w, a3);
            }
            const float bb = sm[OFF_BL1 + jc];
            sm[OFF_O1 + jc * 20 + r3 + 0] = ftanh_(a0 + bb);
            sm[OFF_O1 + jc * 20 + r3 + 1] = ftanh_(a1 + bb);
            sm[OFF_O1 + jc * 20 + r3 + 2] = ftanh_(a2 + bb);
            sm[OFF_O1 + jc * 20 + r3 + 3] = ftanh_(a3 + bb);
        }
        __syncthreads();

        // -- GEMM4: out_t = o1 @ Wl2 + bl2; warp = 4 cols, all lanes active --
        {
            const int row = lane & 15;                      // 0..15
            const int jc  = (wid << 2) + ((lane >> 4) << 1);// wid*4 + half*2
            float a0 = 0.f, a1 = 0.f;
#pragma unroll 4
            for (int k = 0; k < LAT; k++) {
                const float a = sm[OFF_O1 + k * 20 + row];
                const float2 wv = __ldg((const float2*)&Wl2[k * YD + jc]);
                a0 = fmaf(a, wv.x, a0); a1 = fmaf(a, wv.y, a1);
            }
            const float v0 = a0 + sm[OFF_BL2 + jc];
            const float v1 = a1 + sm[OFF_BL2 + jc + 1];
            if (row < nr) {
                float* op = out + (size_t)(b0 + row) * (YD * T_) + (size_t)jc * T_ + t;
                op[0]  = v0;
                op[T_] = v1;
            }
            sm[OFF_YP + jc * 17 + row]       = v0;
            sm[OFF_YP + (jc + 1) * 17 + row] = v1;
        }
        __syncthreads();
    }

    // ---- classifier: sigmoid(relu(h_T @ Wc1 + bc1) @ Wc2 + bc2) ----
    if (has_cls) {
        float* scr = sm + OFF_S0;                            // free after loop
        for (int idx = tid; idx < 16 * CH; idx += NT) {      // 800 = 16r x 50c
            const int r = idx & 15, c = idx >> 4;
            float acc = __ldg(&bc1[c]);
            for (int k = 0; k < LAT; k++)
                acc = fmaf(sm[OFF_H + k * 20 + r], __ldg(&Wc1[k * CH + c]), acc);
            scr[c * 16 + r] = fmaxf(acc, 0.f);
        }
        __syncthreads();
        if (tid < nr) {
            float acc = __ldg(&bc2[0]);
            for (int c = 0; c < CH; c++)
                acc = fmaf(scr[c * 16 + tid], __ldg(&Wc2[c]), acc);
            out[(size_t)B_ * YD * T_ + b0 + tid] = fsig(acc);
        }
    }
}

extern "C" void kernel_launch(void* const* d_in, const int* in_sizes, int n_in,
                              void* d_out, int out_size)
{
    cudaFuncSetAttribute(gru_kernel, cudaFuncAttributeMaxDynamicSharedMemorySize,
                         SMEM_FLOATS * (int)sizeof(float));
    const int has_cls = (out_size > B_ * YD * T_) ? 1 : 0;
    gru_kernel<<<NBK, NT, SMEM_FLOATS * sizeof(float)>>>(
        (const float*)d_in[0],   // x
        (const float*)d_in[1],   // y
        d_in[2],                 // y_mask (dtype auto-detected)
        (const float*)d_in[3],  (const float*)d_in[4],   // Wmu1, bmu1
        (const float*)d_in[5],  (const float*)d_in[6],   // Wmu2, bmu2
        (const float*)d_in[11], (const float*)d_in[12],  // Wih, bih
        (const float*)d_in[13], (const float*)d_in[14],  // Whh, bhh
        (const float*)d_in[15], (const float*)d_in[16],  // Wl1, bl1
        (const float*)d_in[17], (const float*)d_in[18],  // Wl2, bl2
        (const float*)d_in[19], (const float*)d_in[20],  // Wc1, bc1
        (const float*)d_in[21], (const float*)d_in[22],  // Wc2, bc2
        (float*)d_out, has_cls);
}